// round 2
// baseline (speedup 1.0000x reference)
#include <cuda_runtime.h>
#include <cuda_bf16.h>
#include <math.h>
#include <stdint.h>

// ---------------- problem constants ----------------
#define BN    4096          // nodes (B*N)
#define NE    131072        // edges
#define M0V   128
#define M1V   64
#define M2V   32
#define DIMN  480           // 128 + 3*64 + 5*32
#define W3    192           // 3*MSG
#define RBFD  32
#define CUT   5.0f

// ---------------- scratch (device globals; no allocation) ----------------
__device__ float g_x[BN * DIMN];                 // node features, fp32
__device__ float g_rbf[(size_t)NE * RBFD];       // per-edge rbf
__device__ float g_sh[(size_t)NE * 9];           // per-edge sph harmonics
__device__ float g_fcut[NE];                     // per-edge cutoff
__device__ float g_w[(size_t)NE * W3];           // per-edge message weights
__device__ int   g_cnt[BN];
__device__ int   g_off[BN + 1];
__device__ int   g_cur[BN];
__device__ int   g_perm[NE];

// ---------------- node init: x0 = z_emb[z] @ W_in, rest zero ----------------
__global__ void k_init(const int* __restrict__ z, const float* __restrict__ mask,
                       const float* __restrict__ z_emb, const float* __restrict__ W_in) {
    int n = blockIdx.x;
    int t = threadIdx.x;   // 128 threads
    __shared__ float zr[128];
    int zi = z[n];
    zr[t] = z_emb[zi * 128 + t];
    __syncthreads();
    float acc = 0.f;
#pragma unroll 8
    for (int k = 0; k < 128; k++) acc += zr[k] * W_in[k * 128 + t];
    float m = mask[n];
    g_x[(size_t)n * DIMN + t] = acc * m;
    for (int o = 128 + t; o < DIMN; o += 128) g_x[(size_t)n * DIMN + o] = 0.f;
}

// ---------------- per-edge geometry ----------------
__global__ void k_geo(const float* __restrict__ ew, const float* __restrict__ evec) {
    int e = blockIdx.x * 256 + threadIdx.x;
    if (e >= NE) return;
    float len = ew[e];
    float inv = 1.f / fmaxf(len, 1e-8f);
    float x = evec[e * 3 + 0] * inv;
    float y = evec[e * 3 + 1] * inv;
    float zc = evec[e * 3 + 2] * inv;
    float d = fminf(len, CUT);
    const float width = CUT / 31.f;
#pragma unroll
    for (int k = 0; k < RBFD; k++) {
        float c = CUT * (float)k / 31.f;
        float u = (d - c) / width;
        g_rbf[(size_t)e * RBFD + k] = expf(-0.5f * u * u);
    }
    const float s3 = 1.7320508075688772f;
    const float s5 = 2.2360679774997896f;
    const float s15 = 3.872983346207417f;
    float sh[9];
    sh[0] = 1.f;
    sh[1] = s3 * x; sh[2] = s3 * y; sh[3] = s3 * zc;
    sh[4] = s15 * x * y; sh[5] = s15 * y * zc;
    sh[6] = 0.5f * s5 * (3.f * zc * zc - 1.f);
    sh[7] = s15 * x * zc; sh[8] = 0.5f * s15 * (x * x - y * y);
#pragma unroll
    for (int j = 0; j < 9; j++) g_sh[(size_t)e * 9 + j] = sh[j];
    float tt = fminf(len / CUT, 1.f);
    g_fcut[e] = 0.5f * (cosf(3.14159265358979323846f * tt) + 1.f);
}

// ---------------- CSR build ----------------
__global__ void k_zero_cnt() {
    int i = blockIdx.x * 256 + threadIdx.x;
    if (i < BN) g_cnt[i] = 0;
}
__global__ void k_count(const int* __restrict__ dst) {
    int e = blockIdx.x * 256 + threadIdx.x;
    if (e < NE) atomicAdd(&g_cnt[dst[e]], 1);
}
__global__ void k_scan() {   // 1 CTA, 1024 threads, 4 elems each
    __shared__ int part[1024];
    int t = threadIdx.x;
    int base = t * 4;
    int loc[4];
    int s = 0;
#pragma unroll
    for (int i = 0; i < 4; i++) { loc[i] = s; s += g_cnt[base + i]; }
    part[t] = s;
    __syncthreads();
    for (int off = 1; off < 1024; off <<= 1) {
        int v = (t >= off) ? part[t - off] : 0;
        __syncthreads();
        part[t] += v;
        __syncthreads();
    }
    int pre = (t == 0) ? 0 : part[t - 1];
#pragma unroll
    for (int i = 0; i < 4; i++) { g_off[base + i] = pre + loc[i]; g_cur[base + i] = pre + loc[i]; }
    if (t == 1023) g_off[BN] = part[1023];
}
__global__ void k_fill(const int* __restrict__ dst) {
    int e = blockIdx.x * 256 + threadIdx.x;
    if (e < NE) {
        int p = atomicAdd(&g_cur[dst[e]], 1);
        g_perm[p] = e;
    }
}
__global__ void k_sortseg() {   // deterministic order within each segment
    int n = blockIdx.x * 256 + threadIdx.x;
    if (n >= BN) return;
    int lo = g_off[n], hi = g_off[n + 1];
    for (int i = lo + 1; i < hi; i++) {
        int key = g_perm[i];
        int j = i - 1;
        while (j >= lo && g_perm[j] > key) { g_perm[j + 1] = g_perm[j]; j--; }
        g_perm[j + 1] = key;
    }
}

// ---------------- radial MLP per block: g_w = (silu(rbf@rW1+rb1)@rW2 + rb2) * fcut ----------------
// tile: 128 edges, 256 threads. dyn smem layout (floats):
//   sRbfT [32][132]   @0       4224
//   s_rW1 [32*64]     @4224    2048
//   sHT   [64][132]   @6272    8448
//   s_rW2 [64*192]    @14720   12288
//   sFcut [128]       @27008
//   s_rb1 [64]        @27136
//   s_rb2 [192]       @27200   (total 27392 floats = 109568 B)
#define MLP_SMEM_BYTES (27392 * 4)
__global__ void __launch_bounds__(256) k_mlp(const float* __restrict__ rW1b,
                                             const float* __restrict__ rb1b,
                                             const float* __restrict__ rW2b,
                                             const float* __restrict__ rb2b) {
    extern __shared__ float sm[];
    float* sRbfT = sm;
    float* s_rW1 = sm + 4224;
    float* sHT   = sm + 6272;
    float* s_rW2 = sm + 14720;
    float* sFcut = sm + 27008;
    float* s_rb1 = sm + 27136;
    float* s_rb2 = sm + 27200;

    int t = threadIdx.x;
    int e0 = blockIdx.x * 128;

    { // load rbf tile transposed: 2 threads per edge row, 16 floats each
        int i = t >> 1, half = t & 1;
        const float4* r4 = (const float4*)(g_rbf + (size_t)(e0 + i) * RBFD + half * 16);
#pragma unroll
        for (int q = 0; q < 4; q++) {
            float4 v = r4[q];
            int k = half * 16 + q * 4;
            sRbfT[(k + 0) * 132 + i] = v.x;
            sRbfT[(k + 1) * 132 + i] = v.y;
            sRbfT[(k + 2) * 132 + i] = v.z;
            sRbfT[(k + 3) * 132 + i] = v.w;
        }
    }
    for (int q = t; q < 512; q += 256)  ((float4*)s_rW1)[q] = ((const float4*)rW1b)[q];
    for (int q = t; q < 3072; q += 256) ((float4*)s_rW2)[q] = ((const float4*)rW2b)[q];
    if (t < 128) sFcut[t] = g_fcut[e0 + t];
    if (t < 64)  s_rb1[t] = rb1b[t];
    if (t < 192) s_rb2[t] = rb2b[t];
    __syncthreads();

    int tx = t & 15, ty = t >> 4;
    int i0 = ty * 8;

    { // h tile: [128 edges][64], thread computes 8x4
        int c0 = tx * 4;
        float hh[8][4];
#pragma unroll
        for (int a = 0; a < 8; a++)
#pragma unroll
            for (int b = 0; b < 4; b++) hh[a][b] = 0.f;
#pragma unroll 4
        for (int k = 0; k < 32; k++) {
            const float* ar = &sRbfT[k * 132 + i0];
            float4 a0 = *(const float4*)ar;
            float4 a1 = *(const float4*)(ar + 4);
            float4 bv = *(const float4*)&s_rW1[k * 64 + c0];
            float av[8] = {a0.x, a0.y, a0.z, a0.w, a1.x, a1.y, a1.z, a1.w};
            float bb[4] = {bv.x, bv.y, bv.z, bv.w};
#pragma unroll
            for (int a = 0; a < 8; a++)
#pragma unroll
                for (int b = 0; b < 4; b++) hh[a][b] += av[a] * bb[b];
        }
#pragma unroll
        for (int b = 0; b < 4; b++) {
            float rb = s_rb1[c0 + b];
#pragma unroll
            for (int a = 0; a < 8; a++) {
                float v = hh[a][b] + rb;
                v = v / (1.f + expf(-v));      // silu
                sHT[(c0 + b) * 132 + (i0 + a)] = v;
            }
        }
    }
    __syncthreads();

    { // r tile: [128][192], thread 8x12, then * fcut, + rb2 -> g_w
        int j0 = tx * 12;
        float acc[8][12];
#pragma unroll
        for (int a = 0; a < 8; a++)
#pragma unroll
            for (int b = 0; b < 12; b++) acc[a][b] = 0.f;
#pragma unroll 2
        for (int k = 0; k < 64; k++) {
            const float* ar = &sHT[k * 132 + i0];
            float4 a0 = *(const float4*)ar;
            float4 a1 = *(const float4*)(ar + 4);
            const float* br = &s_rW2[k * 192 + j0];
            float4 b0 = *(const float4*)br;
            float4 b1 = *(const float4*)(br + 4);
            float4 b2 = *(const float4*)(br + 8);
            float av[8] = {a0.x, a0.y, a0.z, a0.w, a1.x, a1.y, a1.z, a1.w};
            float bb[12] = {b0.x, b0.y, b0.z, b0.w, b1.x, b1.y, b1.z, b1.w, b2.x, b2.y, b2.z, b2.w};
#pragma unroll
            for (int a = 0; a < 8; a++)
#pragma unroll
                for (int b = 0; b < 12; b++) acc[a][b] += av[a] * bb[b];
        }
        float rb[12];
#pragma unroll
        for (int b = 0; b < 12; b++) rb[b] = s_rb2[j0 + b];
#pragma unroll
        for (int a = 0; a < 8; a++) {
            float f = sFcut[i0 + a];
            float* wout = g_w + (size_t)(e0 + i0 + a) * W3 + j0;
#pragma unroll
            for (int g = 0; g < 3; g++) {
                float4 v;
                v.x = (acc[a][g * 4 + 0] + rb[g * 4 + 0]) * f;
                v.y = (acc[a][g * 4 + 1] + rb[g * 4 + 1]) * f;
                v.z = (acc[a][g * 4 + 2] + rb[g * 4 + 2]) * f;
                v.w = (acc[a][g * 4 + 3] + rb[g * 4 + 3]) * f;
                *(float4*)(wout + g * 4) = v;
            }
        }
    }
}

// ---------------- proj GEMM per block: g_w *= s[edge_src] @ Wp ----------------
// tile: 128 edges x 192 outs, K=128. dyn smem (floats):
//   sAT [128][132] @0       16896   (A transposed, k-major)
//   sWp [128*192]  @16896   24576   (full Wp)
//   total 41472 floats = 165888 B
#define PROJ_SMEM_BYTES (41472 * 4)
__global__ void __launch_bounds__(256) k_proj(const float* __restrict__ Wpb,
                                              const int* __restrict__ esrc) {
    extern __shared__ float sm[];
    float* sAT = sm;
    float* sWp = sm + 16896;
    int t = threadIdx.x;
    int e0 = blockIdx.x * 128;

    { // gather A rows (s = x[:, :128]) transposed into smem
        int i = t >> 1, half = t & 1;
        int src = esrc[e0 + i];
        const float* xr = g_x + (size_t)src * DIMN + half * 64;
#pragma unroll
        for (int q = 0; q < 16; q++) {
            float4 v = *(const float4*)(xr + q * 4);
            int k = half * 64 + q * 4;
            sAT[(k + 0) * 132 + i] = v.x;
            sAT[(k + 1) * 132 + i] = v.y;
            sAT[(k + 2) * 132 + i] = v.z;
            sAT[(k + 3) * 132 + i] = v.w;
        }
    }
    for (int q = t; q < 6144; q += 256) ((float4*)sWp)[q] = ((const float4*)Wpb)[q];
    __syncthreads();

    int tx = t & 15, ty = t >> 4;
    int i0 = ty * 8, j0 = tx * 12;
    float acc[8][12];
#pragma unroll
    for (int a = 0; a < 8; a++)
#pragma unroll
        for (int b = 0; b < 12; b++) acc[a][b] = 0.f;

#pragma unroll 4
    for (int k = 0; k < 128; k++) {
        const float* ar = &sAT[k * 132 + i0];
        float4 a0 = *(const float4*)ar;
        float4 a1 = *(const float4*)(ar + 4);
        const float* br = &sWp[k * 192 + j0];
        float4 b0 = *(const float4*)br;
        float4 b1 = *(const float4*)(br + 4);
        float4 b2 = *(const float4*)(br + 8);
        float av[8] = {a0.x, a0.y, a0.z, a0.w, a1.x, a1.y, a1.z, a1.w};
        float bb[12] = {b0.x, b0.y, b0.z, b0.w, b1.x, b1.y, b1.z, b1.w, b2.x, b2.y, b2.z, b2.w};
#pragma unroll
        for (int a = 0; a < 8; a++)
#pragma unroll
            for (int b = 0; b < 12; b++) acc[a][b] += av[a] * bb[b];
    }

    // epilogue: w *= proj  (RMW on g_w written by k_mlp)
#pragma unroll
    for (int a = 0; a < 8; a++) {
        float* wr = g_w + (size_t)(e0 + i0 + a) * W3 + j0;
#pragma unroll
        for (int g = 0; g < 3; g++) {
            float4 v = *(float4*)(wr + g * 4);
            v.x *= acc[a][g * 4 + 0];
            v.y *= acc[a][g * 4 + 1];
            v.z *= acc[a][g * 4 + 2];
            v.w *= acc[a][g * 4 + 3];
            *(float4*)(wr + g * 4) = v;
        }
    }
}

// ---------------- gather + segment sum + Wo + residual, one CTA per node ----------------
__global__ void __launch_bounds__(192) k_gather(const float* __restrict__ Wo0b,
                                                const float* __restrict__ Wo1b,
                                                const float* __restrict__ Wo2b,
                                                const float* __restrict__ res_scale, int b) {
    __shared__ float sM[576];   // m0[64], m1[64][3], m2[64][5]
    int n = blockIdx.x;
    int t = threadIdx.x;   // 0..191, also the w-column index
    int lo = g_off[n], hi = g_off[n + 1];
    float acc[5] = {0.f, 0.f, 0.f, 0.f, 0.f};
    for (int p = lo; p < hi; p++) {
        int e = g_perm[p];
        float w = g_w[(size_t)e * W3 + t];
        if (t < 64) {
            acc[0] += w;                               // sh[0] == 1
        } else if (t < 128) {
            const float* sh = g_sh + (size_t)e * 9 + 1;
#pragma unroll
            for (int d = 0; d < 3; d++) acc[d] += w * sh[d];
        } else {
            const float* sh = g_sh + (size_t)e * 9 + 4;
#pragma unroll
            for (int d = 0; d < 5; d++) acc[d] += w * sh[d];
        }
    }
    if (t < 64) {
        sM[t] = acc[0];
    } else if (t < 128) {
        int c = t - 64;
#pragma unroll
        for (int d = 0; d < 3; d++) sM[64 + c * 3 + d] = acc[d];
    } else {
        int c = t - 128;
#pragma unroll
        for (int d = 0; d < 5; d++) sM[256 + c * 5 + d] = acc[d];
    }
    __syncthreads();

    float rs = res_scale[b];
    float* xr = g_x + (size_t)n * DIMN;
    for (int o = t; o < DIMN; o += 192) {
        float u = 0.f;
        if (o < 128) {
            int j = o;
#pragma unroll 8
            for (int k = 0; k < 64; k++) u += sM[k] * Wo0b[k * 128 + j];
        } else if (o < 320) {
            int q = o - 128;
            int c = q / 3, d = q - c * 3;
#pragma unroll 8
            for (int k = 0; k < 64; k++) u += sM[64 + k * 3 + d] * Wo1b[k * 64 + c];
        } else {
            int q = o - 320;
            int c = q / 5, d = q - c * 5;
#pragma unroll 8
            for (int k = 0; k < 64; k++) u += sM[256 + k * 5 + d] * Wo2b[k * 32 + c];
        }
        xr[o] += rs * u;
    }
}

// ---------------- irrep RMS norm + mask -> out ----------------
__global__ void __launch_bounds__(256) k_norm(const float* __restrict__ mask,
                                              float* __restrict__ out) {
    __shared__ float r0[256], r1[256], r2[256];
    int n = blockIdx.x, t = threadIdx.x;
    const float* xr = g_x + (size_t)n * DIMN;
    float p0 = 0.f, p1 = 0.f, p2 = 0.f;
    for (int o = t; o < DIMN; o += 256) {
        float v = xr[o];
        float v2 = v * v;
        if (o < 128) p0 += v2;
        else if (o < 320) p1 += v2;
        else p2 += v2;
    }
    r0[t] = p0; r1[t] = p1; r2[t] = p2;
    __syncthreads();
    for (int s = 128; s > 0; s >>= 1) {
        if (t < s) { r0[t] += r0[t + s]; r1[t] += r1[t + s]; r2[t] += r2[t + s]; }
        __syncthreads();
    }
    float inv0 = 1.f / sqrtf(r0[0] / 128.f + 1e-6f);
    float inv1 = 1.f / sqrtf(r1[0] / 64.f + 1e-6f);
    float inv2 = 1.f / sqrtf(r2[0] / 32.f + 1e-6f);
    float m = mask[n];
    for (int o = t; o < DIMN; o += 256) {
        float inv = (o < 128) ? inv0 : ((o < 320) ? inv1 : inv2);
        out[(size_t)n * DIMN + o] = xr[o] * inv * m;
    }
}

// ---------------- launch ----------------
extern "C" void kernel_launch(void* const* d_in, const int* in_sizes, int n_in,
                              void* d_out, int out_size) {
    const int*   z         = (const int*)d_in[0];
    const float* mask      = (const float*)d_in[1];
    const int*   edge_src  = (const int*)d_in[2];
    const int*   edge_dst  = (const int*)d_in[3];
    const float* edge_w    = (const float*)d_in[4];
    const float* edge_vec  = (const float*)d_in[5];
    const float* z_emb     = (const float*)d_in[6];
    const float* W_in      = (const float*)d_in[7];
    const float* Wp        = (const float*)d_in[8];
    const float* rW1       = (const float*)d_in[9];
    const float* rb1       = (const float*)d_in[10];
    const float* rW2       = (const float*)d_in[11];
    const float* rb2       = (const float*)d_in[12];
    const float* Wo0       = (const float*)d_in[13];
    const float* Wo1       = (const float*)d_in[14];
    const float* Wo2       = (const float*)d_in[15];
    const float* res_scale = (const float*)d_in[16];
    float* out = (float*)d_out;

    cudaFuncSetAttribute(k_mlp, cudaFuncAttributeMaxDynamicSharedMemorySize, MLP_SMEM_BYTES);
    cudaFuncSetAttribute(k_proj, cudaFuncAttributeMaxDynamicSharedMemorySize, PROJ_SMEM_BYTES);

    k_init<<<BN, 128>>>(z, mask, z_emb, W_in);
    k_geo<<<NE / 256, 256>>>(edge_w, edge_vec);
    k_zero_cnt<<<BN / 256, 256>>>();
    k_count<<<NE / 256, 256>>>(edge_dst);
    k_scan<<<1, 1024>>>();
    k_fill<<<NE / 256, 256>>>(edge_dst);
    k_sortseg<<<BN / 256, 256>>>();

    for (int b = 0; b < 3; b++) {
        k_mlp<<<NE / 128, 256, MLP_SMEM_BYTES>>>(rW1 + b * 32 * 64, rb1 + b * 64,
                                                 rW2 + b * 64 * 192, rb2 + b * 192);
        k_proj<<<NE / 128, 256, PROJ_SMEM_BYTES>>>(Wp + b * 128 * 192, edge_src);
        k_gather<<<BN, 192>>>(Wo0 + b * 64 * 128, Wo1 + b * 64 * 64, Wo2 + b * 64 * 32,
                              res_scale, b);
    }
    k_norm<<<BN, 256>>>(mask, out);
}

// round 3
// speedup vs baseline: 1.6392x; 1.6392x over previous
#include <cuda_runtime.h>
#include <cuda_bf16.h>
#include <math.h>
#include <stdint.h>

// ---------------- problem constants ----------------
#define BN    4096          // nodes (B*N)
#define NE    131072        // edges
#define DIMN  480           // 128 + 3*64 + 5*32
#define W3    192           // 3*MSG
#define RBFD  32
#define CUT   5.0f

// ---------------- scratch (device globals; no allocation) ----------------
__device__ float g_x[BN * DIMN];                 // node features, fp32
__device__ float g_P[BN * W3];                   // per-node projection x[:, :128] @ Wp
__device__ float g_rbf[(size_t)NE * RBFD];       // per-edge rbf
__device__ float g_sh[(size_t)NE * 9];           // per-edge sph harmonics
__device__ float g_fcut[NE];                     // per-edge cutoff
__device__ float g_w[(size_t)NE * W3];           // per-edge message weights
__device__ int   g_cnt[BN];
__device__ int   g_off[BN + 1];
__device__ int   g_cur[BN];
__device__ int   g_perm[NE];

// ---------------- node init: x0 = z_emb[z] @ W_in, rest zero ----------------
__global__ void k_init(const int* __restrict__ z, const float* __restrict__ mask,
                       const float* __restrict__ z_emb, const float* __restrict__ W_in) {
    int n = blockIdx.x;
    int t = threadIdx.x;   // 128 threads
    __shared__ float zr[128];
    int zi = z[n];
    zr[t] = z_emb[zi * 128 + t];
    __syncthreads();
    float acc = 0.f;
#pragma unroll 8
    for (int k = 0; k < 128; k++) acc += zr[k] * W_in[k * 128 + t];
    float m = mask[n];
    g_x[(size_t)n * DIMN + t] = acc * m;
    for (int o = 128 + t; o < DIMN; o += 128) g_x[(size_t)n * DIMN + o] = 0.f;
}

// ---------------- per-edge geometry ----------------
__global__ void k_geo(const float* __restrict__ ew, const float* __restrict__ evec) {
    int e = blockIdx.x * 256 + threadIdx.x;
    if (e >= NE) return;
    float len = ew[e];
    float inv = 1.f / fmaxf(len, 1e-8f);
    float x = evec[e * 3 + 0] * inv;
    float y = evec[e * 3 + 1] * inv;
    float zc = evec[e * 3 + 2] * inv;
    float d = fminf(len, CUT);
    const float width = CUT / 31.f;
#pragma unroll
    for (int k = 0; k < RBFD; k++) {
        float c = CUT * (float)k / 31.f;
        float u = (d - c) / width;
        g_rbf[(size_t)e * RBFD + k] = expf(-0.5f * u * u);
    }
    const float s3 = 1.7320508075688772f;
    const float s5 = 2.2360679774997896f;
    const float s15 = 3.872983346207417f;
    float sh[9];
    sh[0] = 1.f;
    sh[1] = s3 * x; sh[2] = s3 * y; sh[3] = s3 * zc;
    sh[4] = s15 * x * y; sh[5] = s15 * y * zc;
    sh[6] = 0.5f * s5 * (3.f * zc * zc - 1.f);
    sh[7] = s15 * x * zc; sh[8] = 0.5f * s15 * (x * x - y * y);
#pragma unroll
    for (int j = 0; j < 9; j++) g_sh[(size_t)e * 9 + j] = sh[j];
    float tt = fminf(len / CUT, 1.f);
    g_fcut[e] = 0.5f * (cosf(3.14159265358979323846f * tt) + 1.f);
}

// ---------------- CSR build ----------------
__global__ void k_zero_cnt() {
    int i = blockIdx.x * 256 + threadIdx.x;
    if (i < BN) g_cnt[i] = 0;
}
__global__ void k_count(const int* __restrict__ dst) {
    int e = blockIdx.x * 256 + threadIdx.x;
    if (e < NE) atomicAdd(&g_cnt[dst[e]], 1);
}
__global__ void k_scan() {   // 1 CTA, 1024 threads, 4 elems each
    __shared__ int part[1024];
    int t = threadIdx.x;
    int base = t * 4;
    int loc[4];
    int s = 0;
#pragma unroll
    for (int i = 0; i < 4; i++) { loc[i] = s; s += g_cnt[base + i]; }
    part[t] = s;
    __syncthreads();
    for (int off = 1; off < 1024; off <<= 1) {
        int v = (t >= off) ? part[t - off] : 0;
        __syncthreads();
        part[t] += v;
        __syncthreads();
    }
    int pre = (t == 0) ? 0 : part[t - 1];
#pragma unroll
    for (int i = 0; i < 4; i++) { g_off[base + i] = pre + loc[i]; g_cur[base + i] = pre + loc[i]; }
    if (t == 1023) g_off[BN] = part[1023];
}
__global__ void k_fill(const int* __restrict__ dst) {
    int e = blockIdx.x * 256 + threadIdx.x;
    if (e < NE) {
        int p = atomicAdd(&g_cur[dst[e]], 1);
        g_perm[p] = e;
    }
}
__global__ void k_sortseg() {   // deterministic order within each segment
    int n = blockIdx.x * 256 + threadIdx.x;
    if (n >= BN) return;
    int lo = g_off[n], hi = g_off[n + 1];
    for (int i = lo + 1; i < hi; i++) {
        int key = g_perm[i];
        int j = i - 1;
        while (j >= lo && g_perm[j] > key) { g_perm[j + 1] = g_perm[j]; j--; }
        g_perm[j + 1] = key;
    }
}

// ---------------- per-node proj GEMM: g_P = x[:, :128] @ Wp[b]  (4096x192x128) ----------------
// tile: 64 nodes x 192 cols, K=128. grid=64, 256 threads.
// dyn smem (floats): sAT [128][68] @0 (8704), sWp [128*192] @8704 (24576) -> 33280 fl = 133120 B
#define PROJN_SMEM_BYTES (33280 * 4)
__global__ void __launch_bounds__(256) k_projnode(const float* __restrict__ Wpb) {
    extern __shared__ float sm[];
    float* sAT = sm;
    float* sWp = sm + 8704;
    int t = threadIdx.x;
    int n0 = blockIdx.x * 64;

    { // load A rows (x[:, :128]) transposed: 4 threads per row, 32 floats each
        int i = t >> 2, q = t & 3;
        const float* xr = g_x + (size_t)(n0 + i) * DIMN + q * 32;
#pragma unroll
        for (int r = 0; r < 8; r++) {
            float4 v = *(const float4*)(xr + r * 4);
            int k = q * 32 + r * 4;
            sAT[(k + 0) * 68 + i] = v.x;
            sAT[(k + 1) * 68 + i] = v.y;
            sAT[(k + 2) * 68 + i] = v.z;
            sAT[(k + 3) * 68 + i] = v.w;
        }
    }
    for (int q = t; q < 6144; q += 256) ((float4*)sWp)[q] = ((const float4*)Wpb)[q];
    __syncthreads();

    int tx = t & 15, ty = t >> 4;
    int i0 = ty * 4, j0 = tx * 12;
    float acc[4][12];
#pragma unroll
    for (int a = 0; a < 4; a++)
#pragma unroll
        for (int b = 0; b < 12; b++) acc[a][b] = 0.f;

#pragma unroll 4
    for (int k = 0; k < 128; k++) {
        float4 a0 = *(const float4*)&sAT[k * 68 + i0];
        const float* br = &sWp[k * 192 + j0];
        float4 b0 = *(const float4*)br;
        float4 b1 = *(const float4*)(br + 4);
        float4 b2 = *(const float4*)(br + 8);
        float av[4] = {a0.x, a0.y, a0.z, a0.w};
        float bb[12] = {b0.x, b0.y, b0.z, b0.w, b1.x, b1.y, b1.z, b1.w, b2.x, b2.y, b2.z, b2.w};
#pragma unroll
        for (int a = 0; a < 4; a++)
#pragma unroll
            for (int b = 0; b < 12; b++) acc[a][b] += av[a] * bb[b];
    }
#pragma unroll
    for (int a = 0; a < 4; a++) {
        float* pr = g_P + (size_t)(n0 + i0 + a) * W3 + j0;
#pragma unroll
        for (int g = 0; g < 3; g++) {
            float4 v;
            v.x = acc[a][g * 4 + 0]; v.y = acc[a][g * 4 + 1];
            v.z = acc[a][g * 4 + 2]; v.w = acc[a][g * 4 + 3];
            *(float4*)(pr + g * 4) = v;
        }
    }
}

// ---------------- per-edge: g_w = P[edge_src] * (silu(rbf@rW1+rb1)@rW2 + rb2) * fcut ----------------
// tile: 128 edges, 256 threads. dyn smem layout (floats):
//   sRbfT [32][132]   @0       4224
//   s_rW1 [32*64]     @4224    2048
//   sHT   [64][132]   @6272    8448
//   s_rW2 [64*192]    @14720   12288
//   sFcut [128]       @27008
//   s_rb1 [64]        @27136
//   s_rb2 [192]       @27200
//   s_src [128] (int) @27392   (total 27520 floats = 110080 B)
#define EDGE_SMEM_BYTES (27520 * 4)
__global__ void __launch_bounds__(256) k_edge(const float* __restrict__ rW1b,
                                              const float* __restrict__ rb1b,
                                              const float* __restrict__ rW2b,
                                              const float* __restrict__ rb2b,
                                              const int* __restrict__ esrc) {
    extern __shared__ float sm[];
    float* sRbfT = sm;
    float* s_rW1 = sm + 4224;
    float* sHT   = sm + 6272;
    float* s_rW2 = sm + 14720;
    float* sFcut = sm + 27008;
    float* s_rb1 = sm + 27136;
    float* s_rb2 = sm + 27200;
    int*   s_src = (int*)(sm + 27392);

    int t = threadIdx.x;
    int e0 = blockIdx.x * 128;

    { // load rbf tile transposed: 2 threads per edge row, 16 floats each
        int i = t >> 1, half = t & 1;
        const float4* r4 = (const float4*)(g_rbf + (size_t)(e0 + i) * RBFD + half * 16);
#pragma unroll
        for (int q = 0; q < 4; q++) {
            float4 v = r4[q];
            int k = half * 16 + q * 4;
            sRbfT[(k + 0) * 132 + i] = v.x;
            sRbfT[(k + 1) * 132 + i] = v.y;
            sRbfT[(k + 2) * 132 + i] = v.z;
            sRbfT[(k + 3) * 132 + i] = v.w;
        }
    }
    for (int q = t; q < 512; q += 256)  ((float4*)s_rW1)[q] = ((const float4*)rW1b)[q];
    for (int q = t; q < 3072; q += 256) ((float4*)s_rW2)[q] = ((const float4*)rW2b)[q];
    if (t < 128) { sFcut[t] = g_fcut[e0 + t]; s_src[t] = esrc[e0 + t]; }
    if (t < 64)  s_rb1[t] = rb1b[t];
    if (t >= 64 && t < 256) s_rb2[t - 64] = rb2b[t - 64];
    __syncthreads();

    int tx = t & 15, ty = t >> 4;
    int i0 = ty * 8;

    { // h tile: [128 edges][64], thread computes 8x4
        int c0 = tx * 4;
        float hh[8][4];
#pragma unroll
        for (int a = 0; a < 8; a++)
#pragma unroll
            for (int b = 0; b < 4; b++) hh[a][b] = 0.f;
#pragma unroll 4
        for (int k = 0; k < 32; k++) {
            const float* ar = &sRbfT[k * 132 + i0];
            float4 a0 = *(const float4*)ar;
            float4 a1 = *(const float4*)(ar + 4);
            float4 bv = *(const float4*)&s_rW1[k * 64 + c0];
            float av[8] = {a0.x, a0.y, a0.z, a0.w, a1.x, a1.y, a1.z, a1.w};
            float bb[4] = {bv.x, bv.y, bv.z, bv.w};
#pragma unroll
            for (int a = 0; a < 8; a++)
#pragma unroll
                for (int b = 0; b < 4; b++) hh[a][b] += av[a] * bb[b];
        }
#pragma unroll
        for (int b = 0; b < 4; b++) {
            float rb = s_rb1[c0 + b];
#pragma unroll
            for (int a = 0; a < 8; a++) {
                float v = hh[a][b] + rb;
                v = v / (1.f + expf(-v));      // silu
                sHT[(c0 + b) * 132 + (i0 + a)] = v;
            }
        }
    }
    __syncthreads();

    { // r tile: [128][192], thread 8x12; epilogue: w = P[src] * (r+rb2) * fcut
        int j0 = tx * 12;
        float acc[8][12];
#pragma unroll
        for (int a = 0; a < 8; a++)
#pragma unroll
            for (int b = 0; b < 12; b++) acc[a][b] = 0.f;
#pragma unroll 2
        for (int k = 0; k < 64; k++) {
            const float* ar = &sHT[k * 132 + i0];
            float4 a0 = *(const float4*)ar;
            float4 a1 = *(const float4*)(ar + 4);
            const float* br = &s_rW2[k * 192 + j0];
            float4 b0 = *(const float4*)br;
            float4 b1 = *(const float4*)(br + 4);
            float4 b2 = *(const float4*)(br + 8);
            float av[8] = {a0.x, a0.y, a0.z, a0.w, a1.x, a1.y, a1.z, a1.w};
            float bb[12] = {b0.x, b0.y, b0.z, b0.w, b1.x, b1.y, b1.z, b1.w, b2.x, b2.y, b2.z, b2.w};
#pragma unroll
            for (int a = 0; a < 8; a++)
#pragma unroll
                for (int b = 0; b < 12; b++) acc[a][b] += av[a] * bb[b];
        }
        float rb[12];
#pragma unroll
        for (int b = 0; b < 12; b++) rb[b] = s_rb2[j0 + b];
#pragma unroll
        for (int a = 0; a < 8; a++) {
            float f = sFcut[i0 + a];
            const float* pr = g_P + (size_t)s_src[i0 + a] * W3 + j0;
            float* wout = g_w + (size_t)(e0 + i0 + a) * W3 + j0;
#pragma unroll
            for (int g = 0; g < 3; g++) {
                float4 p = *(const float4*)(pr + g * 4);
                float4 v;
                v.x = (acc[a][g * 4 + 0] + rb[g * 4 + 0]) * f * p.x;
                v.y = (acc[a][g * 4 + 1] + rb[g * 4 + 1]) * f * p.y;
                v.z = (acc[a][g * 4 + 2] + rb[g * 4 + 2]) * f * p.z;
                v.w = (acc[a][g * 4 + 3] + rb[g * 4 + 3]) * f * p.w;
                *(float4*)(wout + g * 4) = v;
            }
        }
    }
}

// ---------------- gather + segment sum + Wo + residual, one CTA per node ----------------
__global__ void __launch_bounds__(192) k_gather(const float* __restrict__ Wo0b,
                                                const float* __restrict__ Wo1b,
                                                const float* __restrict__ Wo2b,
                                                const float* __restrict__ res_scale, int b) {
    __shared__ float sM[576];   // m0[64], m1[64][3], m2[64][5]
    int n = blockIdx.x;
    int t = threadIdx.x;   // 0..191, also the w-column index
    int lo = g_off[n], hi = g_off[n + 1];
    float acc[5] = {0.f, 0.f, 0.f, 0.f, 0.f};
    for (int p = lo; p < hi; p++) {
        int e = g_perm[p];
        float w = g_w[(size_t)e * W3 + t];
        if (t < 64) {
            acc[0] += w;                               // sh[0] == 1
        } else if (t < 128) {
            const float* sh = g_sh + (size_t)e * 9 + 1;
#pragma unroll
            for (int d = 0; d < 3; d++) acc[d] += w * sh[d];
        } else {
            const float* sh = g_sh + (size_t)e * 9 + 4;
#pragma unroll
            for (int d = 0; d < 5; d++) acc[d] += w * sh[d];
        }
    }
    if (t < 64) {
        sM[t] = acc[0];
    } else if (t < 128) {
        int c = t - 64;
#pragma unroll
        for (int d = 0; d < 3; d++) sM[64 + c * 3 + d] = acc[d];
    } else {
        int c = t - 128;
#pragma unroll
        for (int d = 0; d < 5; d++) sM[256 + c * 5 + d] = acc[d];
    }
    __syncthreads();

    float rs = res_scale[b];
    float* xr = g_x + (size_t)n * DIMN;
    for (int o = t; o < DIMN; o += 192) {
        float u = 0.f;
        if (o < 128) {
            int j = o;
#pragma unroll 8
            for (int k = 0; k < 64; k++) u += sM[k] * Wo0b[k * 128 + j];
        } else if (o < 320) {
            int q = o - 128;
            int c = q / 3, d = q - c * 3;
#pragma unroll 8
            for (int k = 0; k < 64; k++) u += sM[64 + k * 3 + d] * Wo1b[k * 64 + c];
        } else {
            int q = o - 320;
            int c = q / 5, d = q - c * 5;
#pragma unroll 8
            for (int k = 0; k < 64; k++) u += sM[256 + k * 5 + d] * Wo2b[k * 32 + c];
        }
        xr[o] += rs * u;
    }
}

// ---------------- irrep RMS norm + mask -> out ----------------
__global__ void __launch_bounds__(256) k_norm(const float* __restrict__ mask,
                                              float* __restrict__ out) {
    __shared__ float r0[256], r1[256], r2[256];
    int n = blockIdx.x, t = threadIdx.x;
    const float* xr = g_x + (size_t)n * DIMN;
    float p0 = 0.f, p1 = 0.f, p2 = 0.f;
    for (int o = t; o < DIMN; o += 256) {
        float v = xr[o];
        float v2 = v * v;
        if (o < 128) p0 += v2;
        else if (o < 320) p1 += v2;
        else p2 += v2;
    }
    r0[t] = p0; r1[t] = p1; r2[t] = p2;
    __syncthreads();
    for (int s = 128; s > 0; s >>= 1) {
        if (t < s) { r0[t] += r0[t + s]; r1[t] += r1[t + s]; r2[t] += r2[t + s]; }
        __syncthreads();
    }
    float inv0 = 1.f / sqrtf(r0[0] / 128.f + 1e-6f);
    float inv1 = 1.f / sqrtf(r1[0] / 64.f + 1e-6f);
    float inv2 = 1.f / sqrtf(r2[0] / 32.f + 1e-6f);
    float m = mask[n];
    for (int o = t; o < DIMN; o += 256) {
        float inv = (o < 128) ? inv0 : ((o < 320) ? inv1 : inv2);
        out[(size_t)n * DIMN + o] = xr[o] * inv * m;
    }
}

// ---------------- launch ----------------
extern "C" void kernel_launch(void* const* d_in, const int* in_sizes, int n_in,
                              void* d_out, int out_size) {
    const int*   z         = (const int*)d_in[0];
    const float* mask      = (const float*)d_in[1];
    const int*   edge_src  = (const int*)d_in[2];
    const int*   edge_dst  = (const int*)d_in[3];
    const float* edge_w    = (const float*)d_in[4];
    const float* edge_vec  = (const float*)d_in[5];
    const float* z_emb     = (const float*)d_in[6];
    const float* W_in      = (const float*)d_in[7];
    const float* Wp        = (const float*)d_in[8];
    const float* rW1       = (const float*)d_in[9];
    const float* rb1       = (const float*)d_in[10];
    const float* rW2       = (const float*)d_in[11];
    const float* rb2       = (const float*)d_in[12];
    const float* Wo0       = (const float*)d_in[13];
    const float* Wo1       = (const float*)d_in[14];
    const float* Wo2       = (const float*)d_in[15];
    const float* res_scale = (const float*)d_in[16];
    float* out = (float*)d_out;

    cudaFuncSetAttribute(k_projnode, cudaFuncAttributeMaxDynamicSharedMemorySize, PROJN_SMEM_BYTES);
    cudaFuncSetAttribute(k_edge, cudaFuncAttributeMaxDynamicSharedMemorySize, EDGE_SMEM_BYTES);

    k_init<<<BN, 128>>>(z, mask, z_emb, W_in);
    k_geo<<<NE / 256, 256>>>(edge_w, edge_vec);
    k_zero_cnt<<<BN / 256, 256>>>();
    k_count<<<NE / 256, 256>>>(edge_dst);
    k_scan<<<1, 1024>>>();
    k_fill<<<NE / 256, 256>>>(edge_dst);
    k_sortseg<<<BN / 256, 256>>>();

    for (int b = 0; b < 3; b++) {
        k_projnode<<<BN / 64, 256, PROJN_SMEM_BYTES>>>(Wp + b * 128 * 192);
        k_edge<<<NE / 128, 256, EDGE_SMEM_BYTES>>>(rW1 + b * 32 * 64, rb1 + b * 64,
                                                   rW2 + b * 64 * 192, rb2 + b * 192,
                                                   edge_src);
        k_gather<<<BN, 192>>>(Wo0 + b * 64 * 128, Wo1 + b * 64 * 64, Wo2 + b * 64 * 32,
                              res_scale, b);
    }
    k_norm<<<BN, 256>>>(mask, out);
}